// round 5
// baseline (speedup 1.0000x reference)
#include <cuda_runtime.h>

// Problem: B=1, H=W=D=128.
// dti: (6,128,128,128) f32 ; ddf: (3,128,128,128) f32 ; out: (6,128,128,128) f32
#define NV (128*128*128)

// 64MB scratch: dti transposed to voxel-major, channels interleaved, padded to 8.
// g_dti8[v*8 + c] = dti[c*NV + v], c in 0..5
__device__ float g_dti8[(size_t)NV * 8];

__device__ __forceinline__ float frcp_a(float x)  { float r; asm("rcp.approx.f32 %0, %1;"   : "=f"(r) : "f"(x)); return r; }
__device__ __forceinline__ float fsqrt_a(float x) { float r; asm("sqrt.approx.f32 %0, %1;"  : "=f"(r) : "f"(x)); return r; }
__device__ __forceinline__ float frsqrt_a(float x){ float r; asm("rsqrt.approx.f32 %0, %1;" : "=f"(r) : "f"(x)); return r; }

// -------- pre-pass: planar (6,NV) -> interleaved (NV,8). Warp writes are
// fully dense: lanes 0..31 cover 1KB contiguous across the two STG.128s. -----
__global__ __launch_bounds__(256)
void interleave_kernel(const float* __restrict__ src)
{
    const int v = blockIdx.x * 256 + threadIdx.x;
    float4 lo, hi;
    lo.x = src[v];
    lo.y = src[NV + v];
    lo.z = src[2 * NV + v];
    lo.w = src[3 * NV + v];
    hi.x = src[4 * NV + v];
    hi.y = src[5 * NV + v];
    hi.z = 0.0f; hi.w = 0.0f;
    float4* dst = (float4*)(g_dti8 + (size_t)v * 8);
    dst[0] = lo;
    dst[1] = hi;
}

__global__ __launch_bounds__(256)
void warp_dti_kernel(const float* __restrict__ dti8,
                     const float* __restrict__ ddf,
                     float* __restrict__ out)
{
    const int v = blockIdx.x * 256 + threadIdx.x;   // grid exactly covers NV
    const int z = v & 127;
    const int y = (v >> 7) & 127;
    const int x = v >> 14;

    // ---------------- displacement at this voxel ----------------
    const float dx = ddf[v];
    const float dy = ddf[NV + v];
    const float dz = ddf[2 * NV + v];

    // ---------------- trilinear warp coords (border clamp) ----------------
    float cx = fminf(fmaxf((float)x + dx, 0.0f), 127.0f);
    float cy = fminf(fmaxf((float)y + dy, 0.0f), 127.0f);
    float cz = fminf(fmaxf((float)z + dz, 0.0f), 127.0f);

    float x0f = floorf(cx), y0f = floorf(cy), z0f = floorf(cz);
    float fx = cx - x0f, fy = cy - y0f, fz = cz - z0f;
    int x0 = (int)x0f, y0 = (int)y0f, z0 = (int)z0f;
    int x1 = min(x0 + 1, 127), y1 = min(y0 + 1, 127), z1 = min(z0 + 1, 127);

    const int i000 = (x0 << 14) | (y0 << 7) | z0;
    const int edz = (z1 - z0) << 3;          // element offset of z+1 block (0 or 8)
    const int edy = (y1 - y0) << 10;         // (dy<<7)*8
    const int edx = (x1 - x0) << 17;         // (dx<<14)*8

    const float gx0 = 1.0f - fx, gy0 = 1.0f - fy;
    const float w00 = gx0 * gy0;
    const float w01 = gx0 * fy;
    const float w10 = fx  * gy0;
    const float w11 = fx  * fy;

    float acc[6] = {0,0,0,0,0,0};
    const float* pb = dti8 + ((size_t)i000 << 3);

    #pragma unroll
    for (int k = 0; k < 4; k++) {
        const int off = (k & 1 ? edy : 0) + (k & 2 ? edx : 0);
        const float wk = (k == 0) ? w00 : (k == 1) ? w01 : (k == 2) ? w10 : w11;
        const float* p = pb + off;          // z0 block (32B aligned)
        const float* q = p + edz;           // z1 block
        float4 a0 = *(const float4*)(p);
        float2 b0 = *(const float2*)(p + 4);
        float4 a1 = *(const float4*)(q);
        float2 b1 = *(const float2*)(q + 4);
        acc[0] = fmaf(wk, fmaf(fz, a1.x - a0.x, a0.x), acc[0]);
        acc[1] = fmaf(wk, fmaf(fz, a1.y - a0.y, a0.y), acc[1]);
        acc[2] = fmaf(wk, fmaf(fz, a1.z - a0.z, a0.z), acc[2]);
        acc[3] = fmaf(wk, fmaf(fz, a1.w - a0.w, a0.w), acc[3]);
        acc[4] = fmaf(wk, fmaf(fz, b1.x - b0.x, b0.x), acc[4]);
        acc[5] = fmaf(wk, fmaf(fz, b1.y - b0.y, b0.y), acc[5]);
    }

    // ---------------- Jacobian J = I + d(ddf)/dx (jnp.gradient semantics) ----
    const int xp = min(x + 1, 127), xm = max(x - 1, 0);
    const int yp = min(y + 1, 127), ym = max(y - 1, 0);
    const int zp = min(z + 1, 127), zm = max(z - 1, 0);
    const float sx = 1.5f - 0.5f * (float)(xp - xm);
    const float sy = 1.5f - 0.5f * (float)(yp - ym);
    const float sz = 1.5f - 0.5f * (float)(zp - zm);

    const int ixp = (xp << 14) | (y << 7) | z;
    const int ixm = (xm << 14) | (y << 7) | z;
    const int iyp = (x << 14) | (yp << 7) | z;
    const int iym = (x << 14) | (ym << 7) | z;
    const int izp = (x << 14) | (y << 7) | zp;
    const int izm = (x << 14) | (y << 7) | zm;

    float X[3][3];
    #pragma unroll
    for (int i = 0; i < 3; i++) {
        const float* p = ddf + i * NV;
        X[i][0] = (p[ixp] - p[ixm]) * sx;
        X[i][1] = (p[iyp] - p[iym]) * sy;
        X[i][2] = (p[izp] - p[izm]) * sz;
    }
    X[0][0] += 1.0f;
    X[1][1] += 1.0f;
    X[2][2] += 1.0f;

    // ---------------- polar factor via Newton iteration ---------------------
    // X <- 0.5*(mu*X + (1/mu)*X^{-T}); Frobenius-optimal mu for first 3 iters,
    // then mu=1 for the last 2 (quadratic convergence finishes it).
    #pragma unroll
    for (int it = 0; it < 5; it++) {
        float C00 = X[1][1] * X[2][2] - X[1][2] * X[2][1];
        float C01 = X[1][2] * X[2][0] - X[1][0] * X[2][2];
        float C02 = X[1][0] * X[2][1] - X[1][1] * X[2][0];
        float C10 = X[0][2] * X[2][1] - X[0][1] * X[2][2];
        float C11 = X[0][0] * X[2][2] - X[0][2] * X[2][0];
        float C12 = X[0][1] * X[2][0] - X[0][0] * X[2][1];
        float C20 = X[0][1] * X[1][2] - X[0][2] * X[1][1];
        float C21 = X[0][2] * X[1][0] - X[0][0] * X[1][2];
        float C22 = X[0][0] * X[1][1] - X[0][1] * X[1][0];

        float det = X[0][0] * C00 + X[0][1] * C01 + X[0][2] * C02;
        float ad = fabsf(det);
        det = (ad < 1e-30f) ? ((det < 0.0f) ? -1e-30f : 1e-30f) : det;
        float rdet = frcp_a(det);

        float ca, cb;
        if (it < 3) {
            float a2 = X[0][0]*X[0][0] + X[0][1]*X[0][1] + X[0][2]*X[0][2]
                     + X[1][0]*X[1][0] + X[1][1]*X[1][1] + X[1][2]*X[1][2]
                     + X[2][0]*X[2][0] + X[2][1]*X[2][1] + X[2][2]*X[2][2];
            float c2s = C00*C00 + C01*C01 + C02*C02
                      + C10*C10 + C11*C11 + C12*C12
                      + C20*C20 + C21*C21 + C22*C22;
            float r = (c2s * rdet * rdet) * frcp_a(a2);
            float t = fsqrt_a(r);
            float mu  = fsqrt_a(t);
            float imu = frsqrt_a(t);
            ca = 0.5f * mu;
            cb = 0.5f * imu * rdet;
        } else {
            ca = 0.5f;
            cb = 0.5f * rdet;
        }

        X[0][0] = ca * X[0][0] + cb * C00;
        X[0][1] = ca * X[0][1] + cb * C01;
        X[0][2] = ca * X[0][2] + cb * C02;
        X[1][0] = ca * X[1][0] + cb * C10;
        X[1][1] = ca * X[1][1] + cb * C11;
        X[1][2] = ca * X[1][2] + cb * C12;
        X[2][0] = ca * X[2][0] + cb * C20;
        X[2][1] = ca * X[2][1] + cb * C21;
        X[2][2] = ca * X[2][2] + cb * C22;
    }

    // ---------------- Dp = R^T M R, M symmetric from warped channels --------
    float M00 = acc[0], M01 = acc[1], M02 = acc[3];
    float M11 = acc[2], M12 = acc[4], M22 = acc[5];

    float A00 = M00 * X[0][0] + M01 * X[1][0] + M02 * X[2][0];
    float A01 = M00 * X[0][1] + M01 * X[1][1] + M02 * X[2][1];
    float A02 = M00 * X[0][2] + M01 * X[1][2] + M02 * X[2][2];
    float A10 = M01 * X[0][0] + M11 * X[1][0] + M12 * X[2][0];
    float A11 = M01 * X[0][1] + M11 * X[1][1] + M12 * X[2][1];
    float A12 = M01 * X[0][2] + M11 * X[1][2] + M12 * X[2][2];
    float A20 = M02 * X[0][0] + M12 * X[1][0] + M22 * X[2][0];
    float A21 = M02 * X[0][1] + M12 * X[1][1] + M22 * X[2][1];
    float A22 = M02 * X[0][2] + M12 * X[1][2] + M22 * X[2][2];

    float Dp00 = X[0][0] * A00 + X[1][0] * A10 + X[2][0] * A20;
    float Dp10 = X[0][1] * A00 + X[1][1] * A10 + X[2][1] * A20;
    float Dp11 = X[0][1] * A01 + X[1][1] * A11 + X[2][1] * A21;
    float Dp20 = X[0][2] * A00 + X[1][2] * A10 + X[2][2] * A20;
    float Dp21 = X[0][2] * A01 + X[1][2] * A11 + X[2][2] * A21;
    float Dp22 = X[0][2] * A02 + X[1][2] * A12 + X[2][2] * A22;

    out[v]          = Dp00;
    out[NV + v]     = Dp10;
    out[2 * NV + v] = Dp11;
    out[3 * NV + v] = Dp20;
    out[4 * NV + v] = Dp21;
    out[5 * NV + v] = Dp22;
}

extern "C" void kernel_launch(void* const* d_in, const int* in_sizes, int n_in,
                              void* d_out, int out_size)
{
    const float* dti = (const float*)d_in[0];   // 6*128^3
    const float* ddf = (const float*)d_in[1];   // 3*128^3
    float* out = (float*)d_out;                 // 6*128^3
    (void)in_sizes; (void)n_in; (void)out_size;

    interleave_kernel<<<NV / 256, 256>>>(dti);

    const float* dti8;
    cudaGetSymbolAddress((void**)&dti8, g_dti8);
    warp_dti_kernel<<<NV / 256, 256>>>(dti8, ddf, out);
}

// round 8
// speedup vs baseline: 1.7404x; 1.7404x over previous
#include <cuda_runtime.h>
#include <cuda_fp16.h>

// Problem: B=1, H=W=D=128.
// dti: (6,128,128,128) f32 ; ddf: (3,128,128,128) f32 ; out: (6,128,128,128) f32
#define NV (128*128*128)

// fp16 interleaved gather arrays (24MB total, half the fp32 footprint):
//   g_q[v] = {h(c0),h(c1),h(c2),h(c3)}  (8B per voxel)
//   g_p[v] = {h(c4),h(c5)}              (4B per voxel)
__device__ uint2    g_q[NV];
__device__ unsigned g_p[NV];

__device__ __forceinline__ float frcp_a(float x)  { float r; asm("rcp.approx.f32 %0, %1;"   : "=f"(r) : "f"(x)); return r; }
__device__ __forceinline__ float fsqrt_a(float x) { float r; asm("sqrt.approx.f32 %0, %1;"  : "=f"(r) : "f"(x)); return r; }
__device__ __forceinline__ float frsqrt_a(float x){ float r; asm("rsqrt.approx.f32 %0, %1;" : "=f"(r) : "f"(x)); return r; }

__device__ __forceinline__ unsigned pack2(float a, float b) {
    __half2 h = __floats2half2_rn(a, b);
    return *(unsigned*)&h;
}
__device__ __forceinline__ float2 up2(unsigned u) {
    __half2 h = *(__half2*)&u;
    return __half22float2(h);
}

// -------- pre-pass: planar fp32 (6,NV) -> interleaved fp16 (NV,4)+(NV,2) ----
__global__ __launch_bounds__(256)
void convert_kernel(const float* __restrict__ src)
{
    const int v = blockIdx.x * 256 + threadIdx.x;
    float c0 = src[v];
    float c1 = src[NV + v];
    float c2 = src[2 * NV + v];
    float c3 = src[3 * NV + v];
    float c4 = src[4 * NV + v];
    float c5 = src[5 * NV + v];
    g_q[v] = make_uint2(pack2(c0, c1), pack2(c2, c3));
    g_p[v] = pack2(c4, c5);
}

__global__ __launch_bounds__(256)
void warp_dti_kernel(const float* __restrict__ ddf,
                     float* __restrict__ out)
{
    const int v = blockIdx.x * 256 + threadIdx.x;   // grid exactly covers NV
    const int z = v & 127;
    const int y = (v >> 7) & 127;
    const int x = v >> 14;

    // ---------------- displacement at this voxel ----------------
    const float dx = ddf[v];
    const float dy = ddf[NV + v];
    const float dz = ddf[2 * NV + v];

    // ---------------- trilinear warp coords (border clamp) ----------------
    float cx = fminf(fmaxf((float)x + dx, 0.0f), 127.0f);
    float cy = fminf(fmaxf((float)y + dy, 0.0f), 127.0f);
    float cz = fminf(fmaxf((float)z + dz, 0.0f), 127.0f);

    float x0f = floorf(cx), y0f = floorf(cy), z0f = floorf(cz);
    float fx = cx - x0f, fy = cy - y0f, fz = cz - z0f;
    int x0 = (int)x0f, y0 = (int)y0f, z0 = (int)z0f;
    int x1 = min(x0 + 1, 127), y1 = min(y0 + 1, 127), z1 = min(z0 + 1, 127);

    const int i000 = (x0 << 14) | (y0 << 7) | z0;
    const int edz = z1 - z0;              // voxel-index deltas
    const int edy = (y1 - y0) << 7;
    const int edx = (x1 - x0) << 14;

    const float gx0 = 1.0f - fx, gy0 = 1.0f - fy;
    const float w00 = gx0 * gy0;
    const float w01 = gx0 * fy;
    const float w10 = fx  * gy0;
    const float w11 = fx  * fy;

    float acc0 = 0, acc1 = 0, acc2 = 0, acc3 = 0, acc4 = 0, acc5 = 0;

    #pragma unroll
    for (int k = 0; k < 4; k++) {
        const int i = i000 + (k & 1 ? edy : 0) + (k & 2 ? edx : 0);
        const float wk = (k == 0) ? w00 : (k == 1) ? w01 : (k == 2) ? w10 : w11;
        const uint2 A0 = g_q[i];
        const uint2 A1 = g_q[i + edz];
        const unsigned B0 = g_p[i];
        const unsigned B1 = g_p[i + edz];
        float2 a01 = up2(A0.x), a23 = up2(A0.y), a45 = up2(B0);
        float2 b01 = up2(A1.x), b23 = up2(A1.y), b45 = up2(B1);
        acc0 = fmaf(wk, fmaf(fz, b01.x - a01.x, a01.x), acc0);
        acc1 = fmaf(wk, fmaf(fz, b01.y - a01.y, a01.y), acc1);
        acc2 = fmaf(wk, fmaf(fz, b23.x - a23.x, a23.x), acc2);
        acc3 = fmaf(wk, fmaf(fz, b23.y - a23.y, a23.y), acc3);
        acc4 = fmaf(wk, fmaf(fz, b45.x - a45.x, a45.x), acc4);
        acc5 = fmaf(wk, fmaf(fz, b45.y - a45.y, a45.y), acc5);
    }

    // ---------------- Jacobian J = I + d(ddf)/dx (jnp.gradient semantics) ----
    const int xp = min(x + 1, 127), xm = max(x - 1, 0);
    const int yp = min(y + 1, 127), ym = max(y - 1, 0);
    const int zp = min(z + 1, 127), zm = max(z - 1, 0);
    const float sx = 1.5f - 0.5f * (float)(xp - xm);
    const float sy = 1.5f - 0.5f * (float)(yp - ym);
    const float sz = 1.5f - 0.5f * (float)(zp - zm);

    const int ixp = (xp << 14) | (y << 7) | z;
    const int ixm = (xm << 14) | (y << 7) | z;
    const int iyp = (x << 14) | (yp << 7) | z;
    const int iym = (x << 14) | (ym << 7) | z;
    const int izp = (x << 14) | (y << 7) | zp;
    const int izm = (x << 14) | (y << 7) | zm;

    float X[3][3];
    #pragma unroll
    for (int i = 0; i < 3; i++) {
        const float* p = ddf + i * NV;
        X[i][0] = (p[ixp] - p[ixm]) * sx;
        X[i][1] = (p[iyp] - p[iym]) * sy;
        X[i][2] = (p[izp] - p[izm]) * sz;
    }
    X[0][0] += 1.0f;
    X[1][1] += 1.0f;
    X[2][2] += 1.0f;

    // ---------------- polar factor via Newton iteration ---------------------
    // X <- 0.5*(mu*X + (1/mu)*X^{-T}); Frobenius-optimal mu for first 3 iters,
    // then mu=1 for the last 2.
    #pragma unroll
    for (int it = 0; it < 5; it++) {
        float C00 = X[1][1] * X[2][2] - X[1][2] * X[2][1];
        float C01 = X[1][2] * X[2][0] - X[1][0] * X[2][2];
        float C02 = X[1][0] * X[2][1] - X[1][1] * X[2][0];
        float C10 = X[0][2] * X[2][1] - X[0][1] * X[2][2];
        float C11 = X[0][0] * X[2][2] - X[0][2] * X[2][0];
        float C12 = X[0][1] * X[2][0] - X[0][0] * X[2][1];
        float C20 = X[0][1] * X[1][2] - X[0][2] * X[1][1];
        float C21 = X[0][2] * X[1][0] - X[0][0] * X[1][2];
        float C22 = X[0][0] * X[1][1] - X[0][1] * X[1][0];

        float det = X[0][0] * C00 + X[0][1] * C01 + X[0][2] * C02;
        float ad = fabsf(det);
        det = (ad < 1e-30f) ? ((det < 0.0f) ? -1e-30f : 1e-30f) : det;
        float rdet = frcp_a(det);

        float ca, cb;
        if (it < 3) {
            float a2 = X[0][0]*X[0][0] + X[0][1]*X[0][1] + X[0][2]*X[0][2]
                     + X[1][0]*X[1][0] + X[1][1]*X[1][1] + X[1][2]*X[1][2]
                     + X[2][0]*X[2][0] + X[2][1]*X[2][1] + X[2][2]*X[2][2];
            float c2s = C00*C00 + C01*C01 + C02*C02
                      + C10*C10 + C11*C11 + C12*C12
                      + C20*C20 + C21*C21 + C22*C22;
            float r = (c2s * rdet * rdet) * frcp_a(a2);
            float t = fsqrt_a(r);
            float mu  = fsqrt_a(t);
            float imu = frsqrt_a(t);
            ca = 0.5f * mu;
            cb = 0.5f * imu * rdet;
        } else {
            ca = 0.5f;
            cb = 0.5f * rdet;
        }

        X[0][0] = ca * X[0][0] + cb * C00;
        X[0][1] = ca * X[0][1] + cb * C01;
        X[0][2] = ca * X[0][2] + cb * C02;
        X[1][0] = ca * X[1][0] + cb * C10;
        X[1][1] = ca * X[1][1] + cb * C11;
        X[1][2] = ca * X[1][2] + cb * C12;
        X[2][0] = ca * X[2][0] + cb * C20;
        X[2][1] = ca * X[2][1] + cb * C21;
        X[2][2] = ca * X[2][2] + cb * C22;
    }

    // ---------------- Dp = R^T M R, M symmetric from warped channels --------
    float M00 = acc0, M01 = acc1, M02 = acc3;
    float M11 = acc2, M12 = acc4, M22 = acc5;

    float A00 = M00 * X[0][0] + M01 * X[1][0] + M02 * X[2][0];
    float A01 = M00 * X[0][1] + M01 * X[1][1] + M02 * X[2][1];
    float A02 = M00 * X[0][2] + M01 * X[1][2] + M02 * X[2][2];
    float A10 = M01 * X[0][0] + M11 * X[1][0] + M12 * X[2][0];
    float A11 = M01 * X[0][1] + M11 * X[1][1] + M12 * X[2][1];
    float A12 = M01 * X[0][2] + M11 * X[1][2] + M12 * X[2][2];
    float A20 = M02 * X[0][0] + M12 * X[1][0] + M22 * X[2][0];
    float A21 = M02 * X[0][1] + M12 * X[1][1] + M22 * X[2][1];
    float A22 = M02 * X[0][2] + M12 * X[1][2] + M22 * X[2][2];

    float Dp00 = X[0][0] * A00 + X[1][0] * A10 + X[2][0] * A20;
    float Dp10 = X[0][1] * A00 + X[1][1] * A10 + X[2][1] * A20;
    float Dp11 = X[0][1] * A01 + X[1][1] * A11 + X[2][1] * A21;
    float Dp20 = X[0][2] * A00 + X[1][2] * A10 + X[2][2] * A20;
    float Dp21 = X[0][2] * A01 + X[1][2] * A11 + X[2][2] * A21;
    float Dp22 = X[0][2] * A02 + X[1][2] * A12 + X[2][2] * A22;

    out[v]          = Dp00;
    out[NV + v]     = Dp10;
    out[2 * NV + v] = Dp11;
    out[3 * NV + v] = Dp20;
    out[4 * NV + v] = Dp21;
    out[5 * NV + v] = Dp22;
}

extern "C" void kernel_launch(void* const* d_in, const int* in_sizes, int n_in,
                              void* d_out, int out_size)
{
    const float* dti = (const float*)d_in[0];   // 6*128^3
    const float* ddf = (const float*)d_in[1];   // 3*128^3
    float* out = (float*)d_out;                 // 6*128^3
    (void)in_sizes; (void)n_in; (void)out_size;

    convert_kernel<<<NV / 256, 256>>>(dti);
    warp_dti_kernel<<<NV / 256, 256>>>(ddf, out);
}

// round 9
// speedup vs baseline: 1.8818x; 1.0812x over previous
#include <cuda_runtime.h>
#include <cuda_fp16.h>

// Problem: B=1, H=W=D=128.
// dti: (6,128,128,128) f32 ; ddf: (3,128,128,128) f32 ; out: (6,128,128,128) f32
#define NV (128*128*128)

// fp16 interleaved gather arrays (24MB total):
//   g_q[v] = {h(c0),h(c1),h(c2),h(c3)}  (8B per voxel)
//   g_p[v] = {h(c4),h(c5)}              (4B per voxel)
__device__ uint2    g_q[NV];
__device__ unsigned g_p[NV];

typedef unsigned long long u64;

__device__ __forceinline__ float frcp_a(float x)  { float r; asm("rcp.approx.f32 %0, %1;"   : "=f"(r) : "f"(x)); return r; }
__device__ __forceinline__ float fsqrt_a(float x) { float r; asm("sqrt.approx.f32 %0, %1;"  : "=f"(r) : "f"(x)); return r; }
__device__ __forceinline__ float frsqrt_a(float x){ float r; asm("rsqrt.approx.f32 %0, %1;" : "=f"(r) : "f"(x)); return r; }

// ---- packed f32x2 helpers (lane0 = low 32 bits = voxel A / first element) ----
__device__ __forceinline__ u64 pk(float lo, float hi) {
    u64 r; asm("mov.b64 %0, {%1,%2};" : "=l"(r) : "f"(lo), "f"(hi)); return r;
}
__device__ __forceinline__ void upk(u64 v, float& lo, float& hi) {
    asm("mov.b64 {%0,%1}, %2;" : "=f"(lo), "=f"(hi) : "l"(v));
}
__device__ __forceinline__ u64 f2mul(u64 a, u64 b) {
    u64 r; asm("mul.rn.f32x2 %0, %1, %2;" : "=l"(r) : "l"(a), "l"(b)); return r;
}
__device__ __forceinline__ u64 f2add(u64 a, u64 b) {
    u64 r; asm("add.rn.f32x2 %0, %1, %2;" : "=l"(r) : "l"(a), "l"(b)); return r;
}
__device__ __forceinline__ u64 f2fma(u64 a, u64 b, u64 c) {
    u64 r; asm("fma.rn.f32x2 %0, %1, %2, %3;" : "=l"(r) : "l"(a), "l"(b), "l"(c)); return r;
}
// exact a-b via FFMA2 with -1 (avoids relying on sub.f32x2 mnemonic)
#define KNEG1 0xBF800000BF800000ULL
#define KONE  0x3F8000003F800000ULL
__device__ __forceinline__ u64 f2sub(u64 a, u64 b) { return f2fma(b, (u64)KNEG1, a); }

__device__ __forceinline__ unsigned pack2h(float a, float b) {
    __half2 h = __floats2half2_rn(a, b);
    return *(unsigned*)&h;
}

// -------- pre-pass: planar fp32 (6,NV) -> interleaved fp16 (NV,4)+(NV,2) ----
__global__ __launch_bounds__(256)
void convert_kernel(const float* __restrict__ src)
{
    const int v = blockIdx.x * 256 + threadIdx.x;
    float c0 = src[v];
    float c1 = src[NV + v];
    float c2 = src[2 * NV + v];
    float c3 = src[3 * NV + v];
    float c4 = src[4 * NV + v];
    float c5 = src[5 * NV + v];
    g_q[v] = make_uint2(pack2h(c0, c1), pack2h(c2, c3));
    g_p[v] = pack2h(c4, c5);
}

// -------- trilinear gather of 6 channels for one voxel.
// Returns channel-pair packed f32x2: a01=(c0,c1), a23=(c2,c3), a45=(c4,c5).
// z-lerp in fp16 (hfma2), xy-weighted sum in packed fp32.
__device__ __forceinline__ void gather6(float cxv, float cyv, float czv,
                                        u64& a01, u64& a23, u64& a45)
{
    float x0f = floorf(cxv), y0f = floorf(cyv), z0f = floorf(czv);
    float fx = cxv - x0f, fy = cyv - y0f, fz = czv - z0f;
    int x0 = (int)x0f, y0 = (int)y0f, z0 = (int)z0f;
    const int edx = (x0 < 127 ? 1 : 0) << 14;
    const int edy = (y0 < 127 ? 1 : 0) << 7;
    const int edz = (z0 < 127 ? 1 : 0);
    const int i000 = (x0 << 14) | (y0 << 7) | z0;

    const __half2 fzh = __float2half2_rn(fz);
    const float gx0 = 1.0f - fx, gy0 = 1.0f - fy;
    const float w[4] = { gx0 * gy0, gx0 * fy, fx * gy0, fx * fy };

    a01 = 0ULL; a23 = 0ULL; a45 = 0ULL;
    #pragma unroll
    for (int k = 0; k < 4; k++) {
        const int i = i000 + ((k & 1) ? edy : 0) + ((k & 2) ? edx : 0);
        const uint2   A0 = g_q[i];
        const uint2   A1 = g_q[i + edz];
        const unsigned B0 = g_p[i];
        const unsigned B1 = g_p[i + edz];
        const u64 wk2 = pk(w[k], w[k]);
        __half2 h01a = *(const __half2*)&A0.x, h01b = *(const __half2*)&A1.x;
        __half2 h23a = *(const __half2*)&A0.y, h23b = *(const __half2*)&A1.y;
        __half2 h45a = *(const __half2*)&B0,   h45b = *(const __half2*)&B1;
        float2 l01 = __half22float2(__hfma2(fzh, __hsub2(h01b, h01a), h01a));
        float2 l23 = __half22float2(__hfma2(fzh, __hsub2(h23b, h23a), h23a));
        float2 l45 = __half22float2(__hfma2(fzh, __hsub2(h45b, h45a), h45a));
        a01 = f2fma(wk2, pk(l01.x, l01.y), a01);
        a23 = f2fma(wk2, pk(l23.x, l23.y), a23);
        a45 = f2fma(wk2, pk(l45.x, l45.y), a45);
    }
}

__global__ __launch_bounds__(256)
void warp_dti_kernel(const float* __restrict__ ddf,
                     float* __restrict__ out)
{
    const int t = blockIdx.x * 256 + threadIdx.x;   // NV/2 threads
    const int v = t << 1;                           // voxel pair (v, v+1)
    const int z = v & 127;                          // even, 0..126
    const int y = (v >> 7) & 127;
    const int x = v >> 14;

    // ---------------- center ddf for both voxels (packed LDG.64) ------------
    const u64 d0 = *(const u64*)(ddf + v);
    const u64 d1 = *(const u64*)(ddf + NV + v);
    const u64 d2 = *(const u64*)(ddf + 2 * NV + v);
    float dxA, dxB, dyA, dyB, dzA, dzB;
    upk(d0, dxA, dxB); upk(d1, dyA, dyB); upk(d2, dzA, dzB);

    // ---------------- trilinear gather per voxel ----------------------------
    u64 q01A, q23A, q45A, q01B, q23B, q45B;
    gather6(fminf(fmaxf((float)x + dxA, 0.0f), 127.0f),
            fminf(fmaxf((float)y + dyA, 0.0f), 127.0f),
            fminf(fmaxf((float)z + dzA, 0.0f), 127.0f), q01A, q23A, q45A);
    gather6(fminf(fmaxf((float)x + dxB, 0.0f), 127.0f),
            fminf(fmaxf((float)y + dyB, 0.0f), 127.0f),
            fminf(fmaxf((float)(z + 1) + dzB, 0.0f), 127.0f), q01B, q23B, q45B);

    // repack channel-pairs -> voxel-pair M entries
    float m0A, m1A, m2A, m3A, m4A, m5A, m0B, m1B, m2B, m3B, m4B, m5B;
    upk(q01A, m0A, m1A); upk(q23A, m2A, m3A); upk(q45A, m4A, m5A);
    upk(q01B, m0B, m1B); upk(q23B, m2B, m3B); upk(q45B, m4B, m5B);
    const u64 M00 = pk(m0A, m0B), M01 = pk(m1A, m1B), M11 = pk(m2A, m2B);
    const u64 M02 = pk(m3A, m3B), M12 = pk(m4A, m4B), M22 = pk(m5A, m5B);

    // ---------------- Jacobian (packed over the voxel pair) -----------------
    const int xp = min(x + 1, 127), xm = max(x - 1, 0);
    const int yp = min(y + 1, 127), ym = max(y - 1, 0);
    const float sxs = 1.5f - 0.5f * (float)(xp - xm);
    const float sys = 1.5f - 0.5f * (float)(yp - ym);
    const float szA = (z == 0)   ? 1.0f : 0.5f;   // voxel A at z (z even)
    const float szB = (z == 126) ? 1.0f : 0.5f;   // voxel B at z+1
    const u64 sx2 = pk(sxs, sxs), sy2 = pk(sys, sys), sz2 = pk(szA, szB);

    const int rowb = (x << 14) | (y << 7);
    const int ixp = (xp << 14) | (y << 7) | z;
    const int ixm = (xm << 14) | (y << 7) | z;
    const int iyp = (x << 14) | (yp << 7) | z;
    const int iym = (x << 14) | (ym << 7) | z;
    const int izm = rowb + max(z - 1, 0);
    const int izp = rowb + min(z + 2, 127);

    u64 X00, X01, X02, X10, X11, X12, X20, X21, X22;
    {
        const u64 cen[3] = { d0, d1, d2 };
        u64 Xr[3][3];
        #pragma unroll
        for (int i = 0; i < 3; i++) {
            const float* p = ddf + i * NV;
            u64 pxp = *(const u64*)(p + ixp);
            u64 pxm = *(const u64*)(p + ixm);
            u64 pyp = *(const u64*)(p + iyp);
            u64 pym = *(const u64*)(p + iym);
            float pzm = p[izm], pzp = p[izp];
            float cl, ch; upk(cen[i], cl, ch);
            Xr[i][0] = f2mul(f2sub(pxp, pxm), sx2);
            Xr[i][1] = f2mul(f2sub(pyp, pym), sy2);
            Xr[i][2] = f2mul(f2sub(pk(ch, pzp), pk(pzm, cl)), sz2);
        }
        X00 = f2add(Xr[0][0], (u64)KONE); X01 = Xr[0][1]; X02 = Xr[0][2];
        X10 = Xr[1][0]; X11 = f2add(Xr[1][1], (u64)KONE); X12 = Xr[1][2];
        X20 = Xr[2][0]; X21 = Xr[2][1]; X22 = f2add(Xr[2][2], (u64)KONE);
    }

    // ---------------- polar factor: packed Newton (2 scaled + 2 plain) ------
    #pragma unroll
    for (int it = 0; it < 4; it++) {
        u64 C00 = f2sub(f2mul(X11, X22), f2mul(X12, X21));
        u64 C01 = f2sub(f2mul(X12, X20), f2mul(X10, X22));
        u64 C02 = f2sub(f2mul(X10, X21), f2mul(X11, X20));
        u64 C10 = f2sub(f2mul(X02, X21), f2mul(X01, X22));
        u64 C11 = f2sub(f2mul(X00, X22), f2mul(X02, X20));
        u64 C12 = f2sub(f2mul(X01, X20), f2mul(X00, X21));
        u64 C20 = f2sub(f2mul(X01, X12), f2mul(X02, X11));
        u64 C21 = f2sub(f2mul(X02, X10), f2mul(X00, X12));
        u64 C22 = f2sub(f2mul(X00, X11), f2mul(X01, X10));

        u64 det2 = f2fma(X00, C00, f2fma(X01, C01, f2mul(X02, C02)));
        float dA, dB; upk(det2, dA, dB);
        dA = (fabsf(dA) < 1e-30f) ? ((dA < 0.0f) ? -1e-30f : 1e-30f) : dA;
        dB = (fabsf(dB) < 1e-30f) ? ((dB < 0.0f) ? -1e-30f : 1e-30f) : dB;
        const float rdA = frcp_a(dA), rdB = frcp_a(dB);

        float caA, caB, cbA, cbB;
        if (it < 2) {
            u64 a2 = f2mul(X00, X00);
            a2 = f2fma(X01, X01, a2); a2 = f2fma(X02, X02, a2);
            a2 = f2fma(X10, X10, a2); a2 = f2fma(X11, X11, a2);
            a2 = f2fma(X12, X12, a2); a2 = f2fma(X20, X20, a2);
            a2 = f2fma(X21, X21, a2); a2 = f2fma(X22, X22, a2);
            u64 c2 = f2mul(C00, C00);
            c2 = f2fma(C01, C01, c2); c2 = f2fma(C02, C02, c2);
            c2 = f2fma(C10, C10, c2); c2 = f2fma(C11, C11, c2);
            c2 = f2fma(C12, C12, c2); c2 = f2fma(C20, C20, c2);
            c2 = f2fma(C21, C21, c2); c2 = f2fma(C22, C22, c2);
            float a2A, a2B, c2A, c2B; upk(a2, a2A, a2B); upk(c2, c2A, c2B);
            float rA = c2A * rdA * rdA * frcp_a(a2A);
            float rB = c2B * rdB * rdB * frcp_a(a2B);
            float tA = fsqrt_a(rA), tB = fsqrt_a(rB);
            caA = 0.5f * fsqrt_a(tA);  caB = 0.5f * fsqrt_a(tB);
            cbA = 0.5f * frsqrt_a(tA) * rdA;
            cbB = 0.5f * frsqrt_a(tB) * rdB;
        } else {
            caA = 0.5f; caB = 0.5f;
            cbA = 0.5f * rdA; cbB = 0.5f * rdB;
        }
        const u64 ca2 = pk(caA, caB), cb2 = pk(cbA, cbB);

        X00 = f2fma(ca2, X00, f2mul(cb2, C00));
        X01 = f2fma(ca2, X01, f2mul(cb2, C01));
        X02 = f2fma(ca2, X02, f2mul(cb2, C02));
        X10 = f2fma(ca2, X10, f2mul(cb2, C10));
        X11 = f2fma(ca2, X11, f2mul(cb2, C11));
        X12 = f2fma(ca2, X12, f2mul(cb2, C12));
        X20 = f2fma(ca2, X20, f2mul(cb2, C20));
        X21 = f2fma(ca2, X21, f2mul(cb2, C21));
        X22 = f2fma(ca2, X22, f2mul(cb2, C22));
    }

    // ---------------- Dp = R^T M R (packed) ----------------------------------
    u64 A00 = f2fma(M00, X00, f2fma(M01, X10, f2mul(M02, X20)));
    u64 A01 = f2fma(M00, X01, f2fma(M01, X11, f2mul(M02, X21)));
    u64 A02 = f2fma(M00, X02, f2fma(M01, X12, f2mul(M02, X22)));
    u64 A10 = f2fma(M01, X00, f2fma(M11, X10, f2mul(M12, X20)));
    u64 A11 = f2fma(M01, X01, f2fma(M11, X11, f2mul(M12, X21)));
    u64 A12 = f2fma(M01, X02, f2fma(M11, X12, f2mul(M12, X22)));
    u64 A20 = f2fma(M02, X00, f2fma(M12, X10, f2mul(M22, X20)));
    u64 A21 = f2fma(M02, X01, f2fma(M12, X11, f2mul(M22, X21)));
    u64 A22 = f2fma(M02, X02, f2fma(M12, X12, f2mul(M22, X22)));

    u64 Dp00 = f2fma(X00, A00, f2fma(X10, A10, f2mul(X20, A20)));
    u64 Dp10 = f2fma(X01, A00, f2fma(X11, A10, f2mul(X21, A20)));
    u64 Dp11 = f2fma(X01, A01, f2fma(X11, A11, f2mul(X21, A21)));
    u64 Dp20 = f2fma(X02, A00, f2fma(X12, A10, f2mul(X22, A20)));
    u64 Dp21 = f2fma(X02, A01, f2fma(X12, A11, f2mul(X22, A21)));
    u64 Dp22 = f2fma(X02, A02, f2fma(X12, A12, f2mul(X22, A22)));

    // packed lane order (lo=v, hi=v+1) matches memory order -> STG.64
    *(u64*)(out + v)          = Dp00;
    *(u64*)(out + NV + v)     = Dp10;
    *(u64*)(out + 2 * NV + v) = Dp11;
    *(u64*)(out + 3 * NV + v) = Dp20;
    *(u64*)(out + 4 * NV + v) = Dp21;
    *(u64*)(out + 5 * NV + v) = Dp22;
}

extern "C" void kernel_launch(void* const* d_in, const int* in_sizes, int n_in,
                              void* d_out, int out_size)
{
    const float* dti = (const float*)d_in[0];   // 6*128^3
    const float* ddf = (const float*)d_in[1];   // 3*128^3
    float* out = (float*)d_out;                 // 6*128^3
    (void)in_sizes; (void)n_in; (void)out_size;

    convert_kernel<<<NV / 256, 256>>>(dti);
    warp_dti_kernel<<<NV / 2 / 256, 256>>>(ddf, out);
}

// round 10
// speedup vs baseline: 1.9976x; 1.0615x over previous
#include <cuda_runtime.h>
#include <cuda_fp16.h>

// Problem: B=1, H=W=D=128.
// dti: (6,128,128,128) f32 ; ddf: (3,128,128,128) f32 ; out: (6,128,128,128) f32
#define NV (128*128*128)

// fp16 interleaved gather arrays (24MB total):
//   g_q[v] = {h(c0),h(c1),h(c2),h(c3)}  (8B per voxel)
//   g_p[v] = {h(c4),h(c5)}              (4B per voxel)
__device__ uint2    g_q[NV];
__device__ unsigned g_p[NV];

typedef unsigned long long u64;

__device__ __forceinline__ float frcp_a(float x)  { float r; asm("rcp.approx.f32 %0, %1;"   : "=f"(r) : "f"(x)); return r; }
__device__ __forceinline__ float fsqrt_a(float x) { float r; asm("sqrt.approx.f32 %0, %1;"  : "=f"(r) : "f"(x)); return r; }
__device__ __forceinline__ float frsqrt_a(float x){ float r; asm("rsqrt.approx.f32 %0, %1;" : "=f"(r) : "f"(x)); return r; }

// ---- packed f32x2 helpers (lane0 = low 32 bits = voxel A / first element) ----
__device__ __forceinline__ u64 pk(float lo, float hi) {
    u64 r; asm("mov.b64 %0, {%1,%2};" : "=l"(r) : "f"(lo), "f"(hi)); return r;
}
__device__ __forceinline__ void upk(u64 v, float& lo, float& hi) {
    asm("mov.b64 {%0,%1}, %2;" : "=f"(lo), "=f"(hi) : "l"(v));
}
__device__ __forceinline__ u64 f2mul(u64 a, u64 b) {
    u64 r; asm("mul.rn.f32x2 %0, %1, %2;" : "=l"(r) : "l"(a), "l"(b)); return r;
}
__device__ __forceinline__ u64 f2add(u64 a, u64 b) {
    u64 r; asm("add.rn.f32x2 %0, %1, %2;" : "=l"(r) : "l"(a), "l"(b)); return r;
}
__device__ __forceinline__ u64 f2fma(u64 a, u64 b, u64 c) {
    u64 r; asm("fma.rn.f32x2 %0, %1, %2, %3;" : "=l"(r) : "l"(a), "l"(b), "l"(c)); return r;
}
// exact a-b via FFMA2 with -1 (avoids relying on sub.f32x2 mnemonic)
#define KNEG1 0xBF800000BF800000ULL
#define KONE  0x3F8000003F800000ULL
__device__ __forceinline__ u64 f2sub(u64 a, u64 b) { return f2fma(b, (u64)KNEG1, a); }

__device__ __forceinline__ unsigned pack2h(float a, float b) {
    __half2 h = __floats2half2_rn(a, b);
    return *(unsigned*)&h;
}

// -------- pre-pass: planar fp32 (6,NV) -> interleaved fp16 (NV,4)+(NV,2) ----
// 4 voxels per thread: 6x LDG.128 in, 3x STG.128 out, fully coalesced.
__global__ __launch_bounds__(256)
void convert_kernel(const float4* __restrict__ src4)
{
    const int j = blockIdx.x * 256 + threadIdx.x;    // [0, NV/4)
    const int Q = NV / 4;
    float4 c0 = src4[j];
    float4 c1 = src4[Q + j];
    float4 c2 = src4[2 * Q + j];
    float4 c3 = src4[3 * Q + j];
    float4 c4 = src4[4 * Q + j];
    float4 c5 = src4[5 * Q + j];
    uint4 qa, qb, pp;
    qa.x = pack2h(c0.x, c1.x); qa.y = pack2h(c2.x, c3.x);
    qa.z = pack2h(c0.y, c1.y); qa.w = pack2h(c2.y, c3.y);
    qb.x = pack2h(c0.z, c1.z); qb.y = pack2h(c2.z, c3.z);
    qb.z = pack2h(c0.w, c1.w); qb.w = pack2h(c2.w, c3.w);
    pp.x = pack2h(c4.x, c5.x); pp.y = pack2h(c4.y, c5.y);
    pp.z = pack2h(c4.z, c5.z); pp.w = pack2h(c4.w, c5.w);
    ((uint4*)g_q)[2 * j]     = qa;
    ((uint4*)g_q)[2 * j + 1] = qb;
    ((uint4*)g_p)[j]         = pp;
}

// -------- trilinear gather of 6 channels for one voxel.
// Returns channel-pair packed f32x2: a01=(c0,c1), a23=(c2,c3), a45=(c4,c5).
// z-lerp in fp16 (hfma2), xy-weighted sum in packed fp32.
__device__ __forceinline__ void gather6(float cxv, float cyv, float czv,
                                        u64& a01, u64& a23, u64& a45)
{
    float x0f = floorf(cxv), y0f = floorf(cyv), z0f = floorf(czv);
    float fx = cxv - x0f, fy = cyv - y0f, fz = czv - z0f;
    int x0 = (int)x0f, y0 = (int)y0f, z0 = (int)z0f;
    const int edx = (x0 < 127 ? 1 : 0) << 14;
    const int edy = (y0 < 127 ? 1 : 0) << 7;
    const int edz = (z0 < 127 ? 1 : 0);
    const int i000 = (x0 << 14) | (y0 << 7) | z0;

    const __half2 fzh = __float2half2_rn(fz);
    const float gx0 = 1.0f - fx, gy0 = 1.0f - fy;
    const float w[4] = { gx0 * gy0, gx0 * fy, fx * gy0, fx * fy };

    a01 = 0ULL; a23 = 0ULL; a45 = 0ULL;
    #pragma unroll
    for (int k = 0; k < 4; k++) {
        const int i = i000 + ((k & 1) ? edy : 0) + ((k & 2) ? edx : 0);
        const uint2   A0 = g_q[i];
        const uint2   A1 = g_q[i + edz];
        const unsigned B0 = g_p[i];
        const unsigned B1 = g_p[i + edz];
        const u64 wk2 = pk(w[k], w[k]);
        __half2 h01a = *(const __half2*)&A0.x, h01b = *(const __half2*)&A1.x;
        __half2 h23a = *(const __half2*)&A0.y, h23b = *(const __half2*)&A1.y;
        __half2 h45a = *(const __half2*)&B0,   h45b = *(const __half2*)&B1;
        float2 l01 = __half22float2(__hfma2(fzh, __hsub2(h01b, h01a), h01a));
        float2 l23 = __half22float2(__hfma2(fzh, __hsub2(h23b, h23a), h23a));
        float2 l45 = __half22float2(__hfma2(fzh, __hsub2(h45b, h45a), h45a));
        a01 = f2fma(wk2, pk(l01.x, l01.y), a01);
        a23 = f2fma(wk2, pk(l23.x, l23.y), a23);
        a45 = f2fma(wk2, pk(l45.x, l45.y), a45);
    }
}

__global__ __launch_bounds__(256, 4)
void warp_dti_kernel(const float* __restrict__ ddf,
                     float* __restrict__ out)
{
    const int t = blockIdx.x * 256 + threadIdx.x;   // NV/2 threads
    const int v = t << 1;                           // voxel pair (v, v+1)
    const int z = v & 127;                          // even, 0..126
    const int y = (v >> 7) & 127;
    const int x = v >> 14;

    // ---------------- center ddf for both voxels (packed LDG.64) ------------
    const u64 d0 = *(const u64*)(ddf + v);
    const u64 d1 = *(const u64*)(ddf + NV + v);
    const u64 d2 = *(const u64*)(ddf + 2 * NV + v);
    float dxA, dxB, dyA, dyB, dzA, dzB;
    upk(d0, dxA, dxB); upk(d1, dyA, dyB); upk(d2, dzA, dzB);

    // ---------------- trilinear gather per voxel ----------------------------
    u64 q01A, q23A, q45A, q01B, q23B, q45B;
    gather6(fminf(fmaxf((float)x + dxA, 0.0f), 127.0f),
            fminf(fmaxf((float)y + dyA, 0.0f), 127.0f),
            fminf(fmaxf((float)z + dzA, 0.0f), 127.0f), q01A, q23A, q45A);
    gather6(fminf(fmaxf((float)x + dxB, 0.0f), 127.0f),
            fminf(fmaxf((float)y + dyB, 0.0f), 127.0f),
            fminf(fmaxf((float)(z + 1) + dzB, 0.0f), 127.0f), q01B, q23B, q45B);

    // repack channel-pairs -> voxel-pair M entries
    float m0A, m1A, m2A, m3A, m4A, m5A, m0B, m1B, m2B, m3B, m4B, m5B;
    upk(q01A, m0A, m1A); upk(q23A, m2A, m3A); upk(q45A, m4A, m5A);
    upk(q01B, m0B, m1B); upk(q23B, m2B, m3B); upk(q45B, m4B, m5B);
    const u64 M00 = pk(m0A, m0B), M01 = pk(m1A, m1B), M11 = pk(m2A, m2B);
    const u64 M02 = pk(m3A, m3B), M12 = pk(m4A, m4B), M22 = pk(m5A, m5B);

    // ---------------- Jacobian (packed over the voxel pair) -----------------
    const int xp = min(x + 1, 127), xm = max(x - 1, 0);
    const int yp = min(y + 1, 127), ym = max(y - 1, 0);
    const float sxs = 1.5f - 0.5f * (float)(xp - xm);
    const float sys = 1.5f - 0.5f * (float)(yp - ym);
    const float szA = (z == 0)   ? 1.0f : 0.5f;   // voxel A at z (z even)
    const float szB = (z == 126) ? 1.0f : 0.5f;   // voxel B at z+1
    const u64 sx2 = pk(sxs, sxs), sy2 = pk(sys, sys), sz2 = pk(szA, szB);

    const int rowb = (x << 14) | (y << 7);
    const int ixp = (xp << 14) | (y << 7) | z;
    const int ixm = (xm << 14) | (y << 7) | z;
    const int iyp = (x << 14) | (yp << 7) | z;
    const int iym = (x << 14) | (ym << 7) | z;
    const int izm = rowb + max(z - 1, 0);
    const int izp = rowb + min(z + 2, 127);

    u64 X00, X01, X02, X10, X11, X12, X20, X21, X22;
    {
        const u64 cen[3] = { d0, d1, d2 };
        u64 Xr[3][3];
        #pragma unroll
        for (int i = 0; i < 3; i++) {
            const float* p = ddf + i * NV;
            u64 pxp = *(const u64*)(p + ixp);
            u64 pxm = *(const u64*)(p + ixm);
            u64 pyp = *(const u64*)(p + iyp);
            u64 pym = *(const u64*)(p + iym);
            float pzm = p[izm], pzp = p[izp];
            float cl, ch; upk(cen[i], cl, ch);
            Xr[i][0] = f2mul(f2sub(pxp, pxm), sx2);
            Xr[i][1] = f2mul(f2sub(pyp, pym), sy2);
            Xr[i][2] = f2mul(f2sub(pk(ch, pzp), pk(pzm, cl)), sz2);
        }
        X00 = f2add(Xr[0][0], (u64)KONE); X01 = Xr[0][1]; X02 = Xr[0][2];
        X10 = Xr[1][0]; X11 = f2add(Xr[1][1], (u64)KONE); X12 = Xr[1][2];
        X20 = Xr[2][0]; X21 = Xr[2][1]; X22 = f2add(Xr[2][2], (u64)KONE);
    }

    // ---------------- polar factor: packed Newton (2 scaled + 2 plain) ------
    #pragma unroll
    for (int it = 0; it < 4; it++) {
        u64 C00 = f2sub(f2mul(X11, X22), f2mul(X12, X21));
        u64 C01 = f2sub(f2mul(X12, X20), f2mul(X10, X22));
        u64 C02 = f2sub(f2mul(X10, X21), f2mul(X11, X20));
        u64 C10 = f2sub(f2mul(X02, X21), f2mul(X01, X22));
        u64 C11 = f2sub(f2mul(X00, X22), f2mul(X02, X20));
        u64 C12 = f2sub(f2mul(X01, X20), f2mul(X00, X21));
        u64 C20 = f2sub(f2mul(X01, X12), f2mul(X02, X11));
        u64 C21 = f2sub(f2mul(X02, X10), f2mul(X00, X12));
        u64 C22 = f2sub(f2mul(X00, X11), f2mul(X01, X10));

        u64 det2 = f2fma(X00, C00, f2fma(X01, C01, f2mul(X02, C02)));
        float dA, dB; upk(det2, dA, dB);
        dA = (fabsf(dA) < 1e-30f) ? ((dA < 0.0f) ? -1e-30f : 1e-30f) : dA;
        dB = (fabsf(dB) < 1e-30f) ? ((dB < 0.0f) ? -1e-30f : 1e-30f) : dB;
        const float rdA = frcp_a(dA), rdB = frcp_a(dB);

        float caA, caB, cbA, cbB;
        if (it < 2) {
            u64 a2 = f2mul(X00, X00);
            a2 = f2fma(X01, X01, a2); a2 = f2fma(X02, X02, a2);
            a2 = f2fma(X10, X10, a2); a2 = f2fma(X11, X11, a2);
            a2 = f2fma(X12, X12, a2); a2 = f2fma(X20, X20, a2);
            a2 = f2fma(X21, X21, a2); a2 = f2fma(X22, X22, a2);
            u64 c2 = f2mul(C00, C00);
            c2 = f2fma(C01, C01, c2); c2 = f2fma(C02, C02, c2);
            c2 = f2fma(C10, C10, c2); c2 = f2fma(C11, C11, c2);
            c2 = f2fma(C12, C12, c2); c2 = f2fma(C20, C20, c2);
            c2 = f2fma(C21, C21, c2); c2 = f2fma(C22, C22, c2);
            float a2A, a2B, c2A, c2B; upk(a2, a2A, a2B); upk(c2, c2A, c2B);
            float rA = c2A * rdA * rdA * frcp_a(a2A);
            float rB = c2B * rdB * rdB * frcp_a(a2B);
            float tA = fsqrt_a(rA), tB = fsqrt_a(rB);
            caA = 0.5f * fsqrt_a(tA);  caB = 0.5f * fsqrt_a(tB);
            cbA = 0.5f * frsqrt_a(tA) * rdA;
            cbB = 0.5f * frsqrt_a(tB) * rdB;
        } else {
            caA = 0.5f; caB = 0.5f;
            cbA = 0.5f * rdA; cbB = 0.5f * rdB;
        }
        const u64 ca2 = pk(caA, caB), cb2 = pk(cbA, cbB);

        X00 = f2fma(ca2, X00, f2mul(cb2, C00));
        X01 = f2fma(ca2, X01, f2mul(cb2, C01));
        X02 = f2fma(ca2, X02, f2mul(cb2, C02));
        X10 = f2fma(ca2, X10, f2mul(cb2, C10));
        X11 = f2fma(ca2, X11, f2mul(cb2, C11));
        X12 = f2fma(ca2, X12, f2mul(cb2, C12));
        X20 = f2fma(ca2, X20, f2mul(cb2, C20));
        X21 = f2fma(ca2, X21, f2mul(cb2, C21));
        X22 = f2fma(ca2, X22, f2mul(cb2, C22));
    }

    // ---------------- Dp = R^T M R (packed) ----------------------------------
    u64 A00 = f2fma(M00, X00, f2fma(M01, X10, f2mul(M02, X20)));
    u64 A01 = f2fma(M00, X01, f2fma(M01, X11, f2mul(M02, X21)));
    u64 A02 = f2fma(M00, X02, f2fma(M01, X12, f2mul(M02, X22)));
    u64 A10 = f2fma(M01, X00, f2fma(M11, X10, f2mul(M12, X20)));
    u64 A11 = f2fma(M01, X01, f2fma(M11, X11, f2mul(M12, X21)));
    u64 A12 = f2fma(M01, X02, f2fma(M11, X12, f2mul(M12, X22)));
    u64 A20 = f2fma(M02, X00, f2fma(M12, X10, f2mul(M22, X20)));
    u64 A21 = f2fma(M02, X01, f2fma(M12, X11, f2mul(M22, X21)));
    u64 A22 = f2fma(M02, X02, f2fma(M12, X12, f2mul(M22, X22)));

    u64 Dp00 = f2fma(X00, A00, f2fma(X10, A10, f2mul(X20, A20)));
    u64 Dp10 = f2fma(X01, A00, f2fma(X11, A10, f2mul(X21, A20)));
    u64 Dp11 = f2fma(X01, A01, f2fma(X11, A11, f2mul(X21, A21)));
    u64 Dp20 = f2fma(X02, A00, f2fma(X12, A10, f2mul(X22, A20)));
    u64 Dp21 = f2fma(X02, A01, f2fma(X12, A11, f2mul(X22, A21)));
    u64 Dp22 = f2fma(X02, A02, f2fma(X12, A12, f2mul(X22, A22)));

    // packed lane order (lo=v, hi=v+1) matches memory order -> STG.64
    *(u64*)(out + v)          = Dp00;
    *(u64*)(out + NV + v)     = Dp10;
    *(u64*)(out + 2 * NV + v) = Dp11;
    *(u64*)(out + 3 * NV + v) = Dp20;
    *(u64*)(out + 4 * NV + v) = Dp21;
    *(u64*)(out + 5 * NV + v) = Dp22;
}

extern "C" void kernel_launch(void* const* d_in, const int* in_sizes, int n_in,
                              void* d_out, int out_size)
{
    const float* dti = (const float*)d_in[0];   // 6*128^3
    const float* ddf = (const float*)d_in[1];   // 3*128^3
    float* out = (float*)d_out;                 // 6*128^3
    (void)in_sizes; (void)n_in; (void)out_size;

    convert_kernel<<<NV / 4 / 256, 256>>>((const float4*)dti);
    warp_dti_kernel<<<NV / 2 / 256, 256>>>(ddf, out);
}